// round 4
// baseline (speedup 1.0000x reference)
#include <cuda_runtime.h>
#include <cstdint>

// x: (2, 3, 256, 256, 256) float32 ; out: (2, 256, 256, 256) float32
//
// out[b,z,y,i] = 0.5 * ( u[b,z,y,(i+1)&255] - u[b,z,y,(i-1)&255]
//                      + v[b,z,(y+1)&255,i] - v[b,z,(y-1)&255,i]
//                      + w[b,(z+1)&255,(y+1)&255,i] - w[b,(z-1)&255,(y-1)&255,i] )
//
// One thread per float4 (R1 shape: 8,388,608 threads, DRAM=87%).
// u edge neighbors come from warp shuffles instead of scalar loads:
// a warp covers 32 consecutive float4s = 128 consecutive floats (half a row),
// so lane k-1's uc.w is lane k's left neighbor, lane k+1's uc.x is the right
// neighbor. Only lane 0 / lane 31 touch the wrap elements (1 predicated
// scalar load each per warp).

#define DIM 256
#define DIMM 255
#define Q 64
#define VOL (DIM * DIM * DIM)

__global__ __launch_bounds__(256) void calc_divergence_kernel(
    const float* __restrict__ x, float* __restrict__ out)
{
    const uint32_t idx = blockIdx.x * blockDim.x + threadIdx.x;
    // decompose: [b:1][z:8][y:8][xq:6]
    const uint32_t xq = idx & (Q - 1);
    const uint32_t y  = (idx >> 6) & DIMM;
    const uint32_t z  = (idx >> 14) & DIMM;
    const uint32_t b  = idx >> 22;

    const uint32_t i0   = xq << 2;        // 0..252, warp-contiguous in chunks of 128
    const uint32_t lane = xq & 31;        // lane within the half-row

    const float* u = x + (size_t)(b * 3 + 0) * VOL;
    const float* v = x + (size_t)(b * 3 + 1) * VOL;
    const float* w = x + (size_t)(b * 3 + 2) * VOL;

    const uint32_t yp = (y + 1) & DIMM;
    const uint32_t ym = (y - 1) & DIMM;
    const uint32_t zp = (z + 1) & DIMM;
    const uint32_t zm = (z - 1) & DIMM;

    // ---- u center ----
    const float* urow = u + ((size_t)z * DIM + y) * DIM;
    const float4 uc = *reinterpret_cast<const float4*>(urow + i0);

    // ---- v / w float4 loads ----
    const float4 vp = *reinterpret_cast<const float4*>(v + ((size_t)z * DIM + yp) * DIM + i0);
    const float4 vm = *reinterpret_cast<const float4*>(v + ((size_t)z * DIM + ym) * DIM + i0);
    const float4 wp = *reinterpret_cast<const float4*>(w + ((size_t)zp * DIM + yp) * DIM + i0);
    const float4 wm = *reinterpret_cast<const float4*>(w + ((size_t)zm * DIM + ym) * DIM + i0);

    // ---- u edges via warp shuffle ----
    // ul = u[i0-1]: lane k gets lane k-1's uc.w; lane 0 loads the wrap element.
    // ur = u[i0+4]: lane k gets lane k+1's uc.x; lane 31 loads the wrap element.
    float ul = __shfl_up_sync(0xFFFFFFFFu, uc.w, 1);
    float ur = __shfl_down_sync(0xFFFFFFFFu, uc.x, 1);
    if (lane == 0)  ul = urow[(i0 - 1) & DIMM];       // i0=0 -> 255, i0=128 -> 127
    if (lane == 31) ur = urow[(i0 + 4) & DIMM];       // i0=124 -> 128, i0=252 -> 0

    float4 r;
    r.x = 0.5f * ((uc.y - ul)   + (vp.x - vm.x) + (wp.x - wm.x));
    r.y = 0.5f * ((uc.z - uc.x) + (vp.y - vm.y) + (wp.y - wm.y));
    r.z = 0.5f * ((uc.w - uc.y) + (vp.z - vm.z) + (wp.z - wm.z));
    r.w = 0.5f * ((ur   - uc.z) + (vp.w - vm.w) + (wp.w - wm.w));

    *reinterpret_cast<float4*>(out + ((size_t)(b * DIM + z) * DIM + y) * DIM + i0) = r;
}

extern "C" void kernel_launch(void* const* d_in, const int* in_sizes, int n_in,
                              void* d_out, int out_size)
{
    const float* x = (const float*)d_in[0];
    float* out = (float*)d_out;

    const uint32_t total_f4 = 2u * DIM * DIM * Q;   // 8,388,608
    const uint32_t threads = 256;
    const uint32_t blocks = total_f4 / threads;     // 32,768

    calc_divergence_kernel<<<blocks, threads>>>(x, out);
}